// round 5
// baseline (speedup 1.0000x reference)
#include <cuda_runtime.h>
#include <cuda_bf16.h>

// LSTM_20452634263894: B=32768, T=512, I=2, H=16.
// 2 batch rows per thread (16384 threads); gates processed in 2 halves of 16
// pairs; i/f/o rows pre-scaled by 0.5 (sigmoid via tanh); f32x2 state update.

#define B_TOT  32768
#define HALF_B 16384
#define T_LEN  512
#define H_DIM  16
#define NTHR   112

typedef unsigned long long u64;

__device__ __forceinline__ u64 pack2(float lo, float hi) {
    u64 r;
    asm("mov.b64 %0, {%1, %2};" : "=l"(r) : "f"(lo), "f"(hi));
    return r;
}
__device__ __forceinline__ void unpack2(u64 v, float& lo, float& hi) {
    asm("mov.b64 {%0, %1}, %2;" : "=f"(lo), "=f"(hi) : "l"(v));
}
__device__ __forceinline__ u64 ffma2(u64 a, u64 b, u64 c) {
    u64 d;
    asm("fma.rn.f32x2 %0, %1, %2, %3;" : "=l"(d) : "l"(a), "l"(b), "l"(c));
    return d;
}
__device__ __forceinline__ u64 mul2(u64 a, u64 b) {
    u64 d;
    asm("mul.rn.f32x2 %0, %1, %2;" : "=l"(d) : "l"(a), "l"(b));
    return d;
}
__device__ __forceinline__ float tanh_fast(float x) {
    float y;
    asm("tanh.approx.f32 %0, %1;" : "=f"(y) : "f"(x));
    return y;
}

// Slot mapping: s in [0,32). hf=s>>4 selects unit-half (units hf*8..hf*8+7).
// s0=s&15: grp=s0>>2 (0=i,1=f,2=g,3=o), j=s0&3. Original gate-pair index
// p = grp*8 + hf*4 + j (gates 2p, 2p+1). i/f/o rows scaled by 0.5.
__device__ __forceinline__ void slot_map(int s, int& p, float& sc) {
    int hf = s >> 4, s0 = s & 15, grp = s0 >> 2, j = s0 & 3;
    p = grp * 8 + hf * 4 + j;
    sc = (grp == 2) ? 1.0f : 0.5f;
}

__global__ void __launch_bounds__(NTHR) lstm_fused2_kernel(
    const float* __restrict__ x,
    const float* __restrict__ W_ih, const float* __restrict__ W_hh,
    const float* __restrict__ b_ih, const float* __restrict__ b_hh,
    const float* __restrict__ W1,  const float* __restrict__ b1,
    const float* __restrict__ W2,  const float* __restrict__ b2,
    float* __restrict__ out)
{
    __shared__ __align__(16) u64 sWhh[H_DIM][32];
    __shared__ __align__(16) u64 sWih[2][32];
    __shared__ __align__(16) u64 sBias[32];
    __shared__ float sW1[H_DIM * H_DIM];
    __shared__ float sb1[H_DIM];
    __shared__ float sW2[2 * H_DIM];
    __shared__ float sb2[2];

    const int tid = threadIdx.x;

    for (int idx = tid; idx < H_DIM * 32; idx += NTHR) {
        int k = idx >> 5, s = idx & 31;
        int p; float sc; slot_map(s, p, sc);
        sWhh[k][s] = pack2(W_hh[(2 * p) * H_DIM + k] * sc,
                           W_hh[(2 * p + 1) * H_DIM + k] * sc);
    }
    for (int idx = tid; idx < 2 * 32; idx += NTHR) {
        int cc = idx >> 5, s = idx & 31;
        int p; float sc; slot_map(s, p, sc);
        sWih[cc][s] = pack2(W_ih[(2 * p) * 2 + cc] * sc,
                            W_ih[(2 * p + 1) * 2 + cc] * sc);
    }
    for (int s = tid; s < 32; s += NTHR) {
        int p; float sc; slot_map(s, p, sc);
        sBias[s] = pack2((b_ih[2 * p] + b_hh[2 * p]) * sc,
                         (b_ih[2 * p + 1] + b_hh[2 * p + 1]) * sc);
    }
    for (int idx = tid; idx < H_DIM * H_DIM; idx += NTHR) sW1[idx] = W1[idx];
    for (int idx = tid; idx < H_DIM; idx += NTHR) sb1[idx] = b1[idx];
    for (int idx = tid; idx < 2 * H_DIM; idx += NTHR) sW2[idx] = W2[idx];
    for (int idx = tid; idx < 2; idx += NTHR) sb2[idx] = b2[idx];
    __syncthreads();

    const int g = blockIdx.x * NTHR + tid;
    if (g >= HALF_B) return;

    const float4* __restrict__ xp0 =
        reinterpret_cast<const float4*>(x + (size_t)g * (T_LEN * 2));
    const float4* __restrict__ xp1 =
        reinterpret_cast<const float4*>(x + (size_t)(g + HALF_B) * (T_LEN * 2));

    float hs[2][H_DIM];       // hidden state, scalar per unit
    u64   cc2[2][8];          // cell state, packed unit pairs
#pragma unroll
    for (int r = 0; r < 2; ++r) {
#pragma unroll
        for (int u = 0; u < H_DIM; ++u) hs[r][u] = 0.0f;
#pragma unroll
        for (int j = 0; j < 8; ++j) cc2[r][j] = 0ull;
    }

    const u64 H05 = pack2(0.5f, 0.5f);

    float4 xb0 = __ldg(xp0);
    float4 xb1 = __ldg(xp1);

#pragma unroll 1
    for (int t2 = 0; t2 < T_LEN / 2; ++t2) {
        float4 xn0, xn1;
        if (t2 + 1 < T_LEN / 2) {
            xn0 = __ldg(xp0 + t2 + 1);
            xn1 = __ldg(xp1 + t2 + 1);
        }

#pragma unroll
        for (int sub = 0; sub < 2; ++sub) {
            const float x00 = sub ? xb0.z : xb0.x;
            const float x01 = sub ? xb0.w : xb0.y;
            const float x10 = sub ? xb1.z : xb1.x;
            const float x11 = sub ? xb1.w : xb1.y;
            const u64 p00 = pack2(x00, x00), p01 = pack2(x01, x01);
            const u64 p10 = pack2(x10, x10), p11 = pack2(x11, x11);

            // hf=0 writes new h for units 0..7 into hn (hf=1 matvec still
            // needs the OLD hs); committed after both halves.
            float hn[2][8];

#pragma unroll
            for (int hf = 0; hf < 2; ++hf) {
                u64 a0[16], a1[16];
                const ulonglong2* __restrict__ bp =
                    reinterpret_cast<const ulonglong2*>(&sBias[hf * 16]);
                const ulonglong2* __restrict__ wp0 =
                    reinterpret_cast<const ulonglong2*>(&sWih[0][hf * 16]);
                const ulonglong2* __restrict__ wp1 =
                    reinterpret_cast<const ulonglong2*>(&sWih[1][hf * 16]);
#pragma unroll
                for (int s2 = 0; s2 < 8; ++s2) {
                    ulonglong2 bb = bp[s2];
                    ulonglong2 w0 = wp0[s2];
                    ulonglong2 w1 = wp1[s2];
                    a0[2 * s2]     = ffma2(p01, w1.x, ffma2(p00, w0.x, bb.x));
                    a0[2 * s2 + 1] = ffma2(p01, w1.y, ffma2(p00, w0.y, bb.y));
                    a1[2 * s2]     = ffma2(p11, w1.x, ffma2(p10, w0.x, bb.x));
                    a1[2 * s2 + 1] = ffma2(p11, w1.y, ffma2(p10, w0.y, bb.y));
                }
#pragma unroll
                for (int k = 0; k < H_DIM; ++k) {
                    const u64 hk0 = pack2(hs[0][k], hs[0][k]);
                    const u64 hk1 = pack2(hs[1][k], hs[1][k]);
                    const ulonglong2* __restrict__ wr =
                        reinterpret_cast<const ulonglong2*>(&sWhh[k][hf * 16]);
#pragma unroll
                    for (int s2 = 0; s2 < 8; ++s2) {
                        ulonglong2 w = wr[s2];
                        a0[2 * s2]     = ffma2(hk0, w.x, a0[2 * s2]);
                        a0[2 * s2 + 1] = ffma2(hk0, w.y, a0[2 * s2 + 1]);
                        a1[2 * s2]     = ffma2(hk1, w.x, a1[2 * s2]);
                        a1[2 * s2 + 1] = ffma2(hk1, w.y, a1[2 * s2 + 1]);
                    }
                }
                // Activation: slots [0..3]=i, [4..7]=f, [8..11]=g, [12..15]=o
                // (i/f/o pre-activations already scaled by 0.5 via weights).
#pragma unroll
                for (int r = 0; r < 2; ++r) {
                    u64* a = r ? a1 : a0;
#pragma unroll
                    for (int j = 0; j < 4; ++j) {
                        float u, v;
                        unpack2(a[j], u, v);
                        u64 i2 = ffma2(H05, pack2(tanh_fast(u), tanh_fast(v)), H05);
                        unpack2(a[4 + j], u, v);
                        u64 f2 = ffma2(H05, pack2(tanh_fast(u), tanh_fast(v)), H05);
                        unpack2(a[8 + j], u, v);
                        u64 g2 = pack2(tanh_fast(u), tanh_fast(v));
                        unpack2(a[12 + j], u, v);
                        u64 o2 = ffma2(H05, pack2(tanh_fast(u), tanh_fast(v)), H05);
                        u64 cn = ffma2(f2, cc2[r][hf * 4 + j], mul2(i2, g2));
                        cc2[r][hf * 4 + j] = cn;
                        unpack2(cn, u, v);
                        u64 hv = mul2(o2, pack2(tanh_fast(u), tanh_fast(v)));
                        float hlo, hhi;
                        unpack2(hv, hlo, hhi);
                        if (hf == 0) {
                            hn[r][2 * j] = hlo; hn[r][2 * j + 1] = hhi;
                        } else {
                            hs[r][8 + 2 * j] = hlo; hs[r][8 + 2 * j + 1] = hhi;
                        }
                    }
                }
            } // hf
            // Commit deferred half-0 hidden updates.
#pragma unroll
            for (int r = 0; r < 2; ++r)
#pragma unroll
                for (int u = 0; u < 8; ++u) hs[r][u] = hn[r][u];
        } // sub
        xb0 = xn0; xb1 = xn1;  // garbage on last iter; never read
    }

    // MLP head: y = tanh(h @ W1^T + b1) @ W2^T + b2
#pragma unroll
    for (int r = 0; r < 2; ++r) {
        float y0 = sb2[0], y1 = sb2[1];
#pragma unroll
        for (int j = 0; j < H_DIM; ++j) {
            float z = sb1[j];
#pragma unroll
            for (int k = 0; k < H_DIM; ++k)
                z = fmaf(hs[r][k], sW1[j * H_DIM + k], z);
            z = tanh_fast(z);
            y0 = fmaf(z, sW2[j], y0);
            y1 = fmaf(z, sW2[H_DIM + j], y1);
        }
        const int row = r ? (g + HALF_B) : g;
        reinterpret_cast<float2*>(out)[row] = make_float2(y0, y1);
    }
}

extern "C" void kernel_launch(void* const* d_in, const int* in_sizes, int n_in,
                              void* d_out, int out_size) {
    const float* x    = (const float*)d_in[0];
    const float* W_ih = (const float*)d_in[1];
    const float* W_hh = (const float*)d_in[2];
    const float* b_ih = (const float*)d_in[3];
    const float* b_hh = (const float*)d_in[4];
    const float* W1   = (const float*)d_in[5];
    const float* b1   = (const float*)d_in[6];
    const float* W2   = (const float*)d_in[7];
    const float* b2   = (const float*)d_in[8];
    float* out = (float*)d_out;

    dim3 block(NTHR);
    dim3 grid((HALF_B + NTHR - 1) / NTHR);  // 147 CTAs -> ~1 per SM
    lstm_fused2_kernel<<<grid, block>>>(x, W_ih, W_hh, b_ih, b_hh,
                                        W1, b1, W2, b2, out);
}

// round 7
// speedup vs baseline: 1.9339x; 1.9339x over previous
#include <cuda_runtime.h>
#include <cuda_bf16.h>

// LSTM_20452634263894: B=32768, T=512, I=2, H=16.
// Thread-pair gate split: even lane computes units 0-7, odd lane units 8-15,
// each for a PAIR of batch rows. Per-thread work == R0 (no spills), but each
// weight LDS.128 feeds 4 FMAs (2 parities share the wavefront, 2 rows share
// the register). h exchanged across the pair via shfl.bfly each step.
// i/f/o weight rows pre-scaled by 0.5 (sigmoid = 0.5*tanh(0.5x)+0.5).

#define B_TOT  32768
#define T_LEN  512
#define H_DIM  16
#define NTHR   128

typedef unsigned long long u64;

__device__ __forceinline__ u64 pack2(float lo, float hi) {
    u64 r;
    asm("mov.b64 %0, {%1, %2};" : "=l"(r) : "f"(lo), "f"(hi));
    return r;
}
__device__ __forceinline__ void unpack2(u64 v, float& lo, float& hi) {
    asm("mov.b64 {%0, %1}, %2;" : "=f"(lo), "=f"(hi) : "l"(v));
}
__device__ __forceinline__ u64 ffma2(u64 a, u64 b, u64 c) {
    u64 d;
    asm("fma.rn.f32x2 %0, %1, %2, %3;" : "=l"(d) : "l"(a), "l"(b), "l"(c));
    return d;
}
__device__ __forceinline__ u64 mul2(u64 a, u64 b) {
    u64 d;
    asm("mul.rn.f32x2 %0, %1, %2;" : "=l"(d) : "l"(a), "l"(b));
    return d;
}
__device__ __forceinline__ float tanh_fast(float x) {
    float y;
    asm("tanh.approx.f32 %0, %1;" : "=f"(y) : "f"(x));
    return y;
}

// Per-thread slot s in [0,16): grp = s>>2 (0=i,1=f,2=g,3=o), jj = s&3.
// Global gate-pair p = grp*8 + parity*4 + jj  (gates 2p, 2p+1 = units
// parity*8 + 2jj, +1 of gate-type grp). i/f/o scaled by 0.5.
// Smem u64 layout per weight row (32 u64 = 256B): entry
//   e = 4*(s>>1) + 2*parity + (s&1)
// so a thread's slot-pair j lives at ulonglong2 index (2j + parity):
// even lanes hit byte j*32, odd lanes j*32+16 -> disjoint banks, 1 wavefront.
__device__ __forceinline__ void decode_entry(int e, int& p, float& sc) {
    int j2 = e >> 2, par = (e >> 1) & 1, lane = e & 1;
    int s = 2 * j2 + lane;
    int grp = s >> 2, jj = s & 3;
    p = grp * 8 + par * 4 + jj;
    sc = (grp == 2) ? 1.0f : 0.5f;
}

__global__ void __launch_bounds__(NTHR, 2) lstm_split_kernel(
    const float* __restrict__ x,
    const float* __restrict__ W_ih, const float* __restrict__ W_hh,
    const float* __restrict__ b_ih, const float* __restrict__ b_hh,
    const float* __restrict__ W1,  const float* __restrict__ b1,
    const float* __restrict__ W2,  const float* __restrict__ b2,
    float* __restrict__ out)
{
    __shared__ __align__(16) u64 sWhh[H_DIM][32];
    __shared__ __align__(16) u64 sWih[2][32];
    __shared__ __align__(16) u64 sBias[32];
    __shared__ float sW1[H_DIM * H_DIM];
    __shared__ float sb1[H_DIM];
    __shared__ float sW2[2 * H_DIM];
    __shared__ float sb2[2];

    const int tid = threadIdx.x;

    for (int idx = tid; idx < H_DIM * 32; idx += NTHR) {
        int k = idx >> 5, e = idx & 31;
        int p; float sc; decode_entry(e, p, sc);
        sWhh[k][e] = pack2(W_hh[(2 * p) * H_DIM + k] * sc,
                           W_hh[(2 * p + 1) * H_DIM + k] * sc);
    }
    for (int idx = tid; idx < 2 * 32; idx += NTHR) {
        int cc = idx >> 5, e = idx & 31;
        int p; float sc; decode_entry(e, p, sc);
        sWih[cc][e] = pack2(W_ih[(2 * p) * 2 + cc] * sc,
                            W_ih[(2 * p + 1) * 2 + cc] * sc);
    }
    for (int e = tid; e < 32; e += NTHR) {
        int p; float sc; decode_entry(e, p, sc);
        sBias[e] = pack2((b_ih[2 * p] + b_hh[2 * p]) * sc,
                         (b_ih[2 * p + 1] + b_hh[2 * p + 1]) * sc);
    }
    for (int idx = tid; idx < H_DIM * H_DIM; idx += NTHR) sW1[idx] = W1[idx];
    for (int idx = tid; idx < H_DIM; idx += NTHR) sb1[idx] = b1[idx];
    for (int idx = tid; idx < 2 * H_DIM; idx += NTHR) sW2[idx] = W2[idx];
    for (int idx = tid; idx < 2; idx += NTHR) sb2[idx] = b2[idx];
    __syncthreads();

    const int gt     = blockIdx.x * NTHR + tid;   // 32768 threads total
    const int pairId = gt >> 1;
    const int parity = gt & 1;
    const int rowA   = 2 * pairId;
    const int rowB   = 2 * pairId + 1;

    const float4* __restrict__ xpA =
        reinterpret_cast<const float4*>(x + (size_t)rowA * (T_LEN * 2));
    const float4* __restrict__ xpB =
        reinterpret_cast<const float4*>(x + (size_t)rowB * (T_LEN * 2));

    float hA[H_DIM], hB[H_DIM];   // full hidden state, both rows
    u64   cA[4], cB[4];           // cell state, OWN 8 units as 4 pairs
#pragma unroll
    for (int u = 0; u < H_DIM; ++u) { hA[u] = 0.0f; hB[u] = 0.0f; }
#pragma unroll
    for (int j = 0; j < 4; ++j) { cA[j] = 0ull; cB[j] = 0ull; }

    const u64 H05 = pack2(0.5f, 0.5f);
    const int myu = parity * 8;     // first owned unit
    const int otu = 8 - myu;        // partner's first unit

    float4 xbA = __ldg(xpA);
    float4 xbB = __ldg(xpB);

#pragma unroll 1
    for (int t2 = 0; t2 < T_LEN / 2; ++t2) {
        float4 xnA, xnB;
        if (t2 + 1 < T_LEN / 2) {
            xnA = __ldg(xpA + t2 + 1);
            xnB = __ldg(xpB + t2 + 1);
        }

#pragma unroll
        for (int sub = 0; sub < 2; ++sub) {
            const float xA0 = sub ? xbA.z : xbA.x;
            const float xA1 = sub ? xbA.w : xbA.y;
            const float xB0 = sub ? xbB.z : xbB.x;
            const float xB1 = sub ? xbB.w : xbB.y;
            const u64 pA0 = pack2(xA0, xA0), pA1 = pack2(xA1, xA1);
            const u64 pB0 = pack2(xB0, xB0), pB1 = pack2(xB1, xB1);

            u64 aA[16], aB[16];   // 16 slots (own 8 units x 4 gate types)

            const ulonglong2* __restrict__ bp =
                reinterpret_cast<const ulonglong2*>(&sBias[0]);
            const ulonglong2* __restrict__ wp0 =
                reinterpret_cast<const ulonglong2*>(&sWih[0][0]);
            const ulonglong2* __restrict__ wp1 =
                reinterpret_cast<const ulonglong2*>(&sWih[1][0]);
#pragma unroll
            for (int j = 0; j < 8; ++j) {
                const int e = 2 * j + parity;
                ulonglong2 bb = bp[e];
                ulonglong2 w0 = wp0[e];
                ulonglong2 w1 = wp1[e];
                aA[2 * j]     = ffma2(pA1, w1.x, ffma2(pA0, w0.x, bb.x));
                aA[2 * j + 1] = ffma2(pA1, w1.y, ffma2(pA0, w0.y, bb.y));
                aB[2 * j]     = ffma2(pB1, w1.x, ffma2(pB0, w0.x, bb.x));
                aB[2 * j + 1] = ffma2(pB1, w1.y, ffma2(pB0, w0.y, bb.y));
            }

            // Recurrent matvec: each LDS.128 feeds 4 ffma2 (2 rows x 2 slots)
#pragma unroll
            for (int k = 0; k < H_DIM; ++k) {
                const u64 hkA = pack2(hA[k], hA[k]);
                const u64 hkB = pack2(hB[k], hB[k]);
                const ulonglong2* __restrict__ wr =
                    reinterpret_cast<const ulonglong2*>(&sWhh[k][0]);
#pragma unroll
                for (int j = 0; j < 8; ++j) {
                    ulonglong2 w = wr[2 * j + parity];
                    aA[2 * j]     = ffma2(hkA, w.x, aA[2 * j]);
                    aA[2 * j + 1] = ffma2(hkA, w.y, aA[2 * j + 1]);
                    aB[2 * j]     = ffma2(hkB, w.x, aB[2 * j]);
                    aB[2 * j + 1] = ffma2(hkB, w.y, aB[2 * j + 1]);
                }
            }

            // Activation for own 8 units (4 unit-pairs), both rows.
            // Slots: [0..3]=i, [4..7]=f, [8..11]=g, [12..15]=o.
            float hnA[8], hnB[8];
#pragma unroll
            for (int r = 0; r < 2; ++r) {
                u64* a  = r ? aB : aA;
                u64* cc = r ? cB : cA;
                float* hn = r ? hnB : hnA;
#pragma unroll
                for (int j = 0; j < 4; ++j) {
                    float u, v;
                    unpack2(a[j], u, v);
                    u64 i2 = ffma2(H05, pack2(tanh_fast(u), tanh_fast(v)), H05);
                    unpack2(a[4 + j], u, v);
                    u64 f2 = ffma2(H05, pack2(tanh_fast(u), tanh_fast(v)), H05);
                    unpack2(a[8 + j], u, v);
                    u64 g2 = pack2(tanh_fast(u), tanh_fast(v));
                    unpack2(a[12 + j], u, v);
                    u64 o2 = ffma2(H05, pack2(tanh_fast(u), tanh_fast(v)), H05);
                    u64 cn = ffma2(f2, cc[j], mul2(i2, g2));
                    cc[j] = cn;
                    unpack2(cn, u, v);
                    u64 hv = mul2(o2, pack2(tanh_fast(u), tanh_fast(v)));
                    unpack2(hv, hn[2 * j], hn[2 * j + 1]);
                }
            }

            // Exchange: own units -> hs directly, partner units via shfl.bfly.
#pragma unroll
            for (int u = 0; u < 8; ++u) {
                hA[myu + u] = hnA[u];
                hB[myu + u] = hnB[u];
                hA[otu + u] = __shfl_xor_sync(0xffffffffu, hnA[u], 1);
                hB[otu + u] = __shfl_xor_sync(0xffffffffu, hnB[u], 1);
            }
        } // sub
        xbA = xnA; xbB = xnB;  // dead on last iter
    }

    // MLP head: even lane writes row A, odd lane writes row B.
    const float* hs = parity ? hB : hA;
    float y0 = sb2[0], y1 = sb2[1];
#pragma unroll
    for (int j = 0; j < H_DIM; ++j) {
        float z = sb1[j];
#pragma unroll
        for (int k = 0; k < H_DIM; ++k)
            z = fmaf(hs[k], sW1[j * H_DIM + k], z);
        z = tanh_fast(z);
        y0 = fmaf(z, sW2[j], y0);
        y1 = fmaf(z, sW2[H_DIM + j], y1);
    }
    const int orow = parity ? rowB : rowA;
    reinterpret_cast<float2*>(out)[orow] = make_float2(y0, y1);
}

extern "C" void kernel_launch(void* const* d_in, const int* in_sizes, int n_in,
                              void* d_out, int out_size) {
    const float* x    = (const float*)d_in[0];
    const float* W_ih = (const float*)d_in[1];
    const float* W_hh = (const float*)d_in[2];
    const float* b_ih = (const float*)d_in[3];
    const float* b_hh = (const float*)d_in[4];
    const float* W1   = (const float*)d_in[5];
    const float* b1   = (const float*)d_in[6];
    const float* W2   = (const float*)d_in[7];
    const float* b2   = (const float*)d_in[8];
    float* out = (float*)d_out;

    dim3 block(NTHR);
    dim3 grid(B_TOT / NTHR);   // 256 CTAs x 128 threads = 32768 threads
    lstm_split_kernel<<<grid, block>>>(x, W_ih, W_hh, b_ih, b_hh,
                                       W1, b1, W2, b2, out);
}